// round 12
// baseline (speedup 1.0000x reference)
#include <cuda_runtime.h>
#include <cuda_bf16.h>

// Problem constants
#define BB 64      // batch
#define NN 512     // tokens
#define EE 512     // embed dim
#define DD 1024    // 2E
#define TT 64      // decode steps

typedef unsigned long long ull;

// ---------------- device scratch ----------------
__device__ float g_enc[(size_t)BB * EE * NN];   // [b][e][n]  64 MB, L2-resident
__device__ float g_dec_t[DD * BB];              // step-0 decoder input, TRANSPOSED [k][b]
__device__ float g_hx_t[EE * BB];               // hx transposed [e(=k')][b]
__device__ float g_qpart[4][BB][EE];            // q partials [ks][b][e]
__device__ float g_scores[BB * NN];
__device__ float g_wsum;                        // sum of wr

// ---------------- packed fp32x2 helpers (sm_103a FFMA2) ----------------
__device__ __forceinline__ ull pack2(float x, float y) {
    ull r; asm("mov.b64 %0, {%1,%2};" : "=l"(r) : "f"(x), "f"(y)); return r;
}
__device__ __forceinline__ void unpack2(ull v, float& x, float& y) {
    asm("mov.b64 {%0,%1}, %2;" : "=f"(x), "=f"(y) : "l"(v));
}
__device__ __forceinline__ void ffma2(ull& d, ull a, ull b) {
    asm("fma.rn.f32x2 %0, %1, %2, %0;" : "+l"(d) : "l"(a), "l"(b));
}
__device__ __forceinline__ float ex2a(float x) {
    float r; asm("ex2.approx.f32 %0, %1;" : "=f"(r) : "f"(x)); return r;
}
__device__ __forceinline__ float rcpa(float x) {
    float r; asm("rcp.approx.f32 %0, %1;" : "=f"(r) : "f"(x)); return r;
}

#define C2L 2.885390081777926f   // 2*log2(e)

// =====================================================================
// K1: enc[b][e][n] = be[e] + sum_d te[b][n][d] * We[e][d]
// (EXACT R10 version — measured 753us, ~fp32 FFMA2 roofline)
// =====================================================================
__global__ __launch_bounds__(256) void enc_kernel(
    const float* __restrict__ te, const float* __restrict__ We,
    const float* __restrict__ be)
{
    const int b  = blockIdx.z;
    const int n0 = blockIdx.x * 128;
    const int e0 = blockIdx.y * 128;

    __shared__ __align__(16) float As[16][132];
    __shared__ __align__(16) float Bs[16][132];

    const int tid = threadIdx.x;
    const int ty  = tid >> 4;
    const int tx  = tid & 15;

    ull acc[8][4];
#pragma unroll
    for (int i = 0; i < 8; i++)
#pragma unroll
        for (int j = 0; j < 4; j++) acc[i][j] = 0ULL;

    const int lrow = tid >> 2;
    const int lk4  = (tid & 3) * 4;
    const float* Aptr = We + (size_t)(e0 + lrow) * DD + lk4;
    const float* Bptr = te + ((size_t)b * NN + (n0 + lrow)) * DD + lk4;

    for (int k0 = 0; k0 < DD; k0 += 16) {
        float4 a0 = *(const float4*)(Aptr + k0);
        float4 a1 = *(const float4*)(Aptr + k0 + (size_t)64 * DD);
        float4 c0 = *(const float4*)(Bptr + k0);
        float4 c1 = *(const float4*)(Bptr + k0 + (size_t)64 * DD);
        As[lk4 + 0][lrow]      = a0.x; As[lk4 + 1][lrow]      = a0.y;
        As[lk4 + 2][lrow]      = a0.z; As[lk4 + 3][lrow]      = a0.w;
        As[lk4 + 0][lrow + 64] = a1.x; As[lk4 + 1][lrow + 64] = a1.y;
        As[lk4 + 2][lrow + 64] = a1.z; As[lk4 + 3][lrow + 64] = a1.w;
        Bs[lk4 + 0][lrow]      = c0.x; Bs[lk4 + 1][lrow]      = c0.y;
        Bs[lk4 + 2][lrow]      = c0.z; Bs[lk4 + 3][lrow]      = c0.w;
        Bs[lk4 + 0][lrow + 64] = c1.x; Bs[lk4 + 1][lrow + 64] = c1.y;
        Bs[lk4 + 2][lrow + 64] = c1.z; Bs[lk4 + 3][lrow + 64] = c1.w;
        __syncthreads();

#pragma unroll
        for (int kk = 0; kk < 16; kk++) {
            float4 av0 = *(const float4*)&As[kk][ty * 8];
            float4 av1 = *(const float4*)&As[kk][ty * 8 + 4];
            float4 bv0 = *(const float4*)&Bs[kk][tx * 8];
            float4 bv1 = *(const float4*)&Bs[kk][tx * 8 + 4];
            ull bp0 = pack2(bv0.x, bv0.y);
            ull bp1 = pack2(bv0.z, bv0.w);
            ull bp2 = pack2(bv1.x, bv1.y);
            ull bp3 = pack2(bv1.z, bv1.w);
            float av[8] = {av0.x, av0.y, av0.z, av0.w, av1.x, av1.y, av1.z, av1.w};
#pragma unroll
            for (int i = 0; i < 8; i++) {
                ull ad = pack2(av[i], av[i]);
                ffma2(acc[i][0], ad, bp0);
                ffma2(acc[i][1], ad, bp1);
                ffma2(acc[i][2], ad, bp2);
                ffma2(acc[i][3], ad, bp3);
            }
        }
        __syncthreads();
    }

#pragma unroll
    for (int i = 0; i < 8; i++) {
        const int e = e0 + ty * 8 + i;
        const float bias = __ldg(&be[e]);
        float* orow = g_enc + ((size_t)b * EE + e) * NN + n0 + tx * 8;
#pragma unroll
        for (int j = 0; j < 4; j++) {
            float x, y;
            unpack2(acc[i][j], x, y);
            float2 v = make_float2(x + bias, y + bias);
            *(float2*)(orow + 2 * j) = v;
        }
    }
}

// =====================================================================
// K0: g_dec_t[k][b] <- encoded_document[b][k]; block 0 also reduces wr.
// grid 64, block 256
// =====================================================================
__global__ __launch_bounds__(256) void init_kernel(
    const float* __restrict__ encdoc, const float* __restrict__ wr)
{
    const int b = blockIdx.x, t = threadIdx.x;
#pragma unroll
    for (int i = 0; i < 4; i++) {
        const int k = i * 256 + t;
        g_dec_t[k * BB + b] = encdoc[(size_t)b * DD + k];
    }
    if (b == 0) {
        __shared__ float red[256];
        red[t] = __ldg(&wr[t]) + __ldg(&wr[t + 256]);
        __syncthreads();
#pragma unroll
        for (int o = 128; o > 0; o >>= 1) {
            if (t < o) red[t] += red[t + o];
            __syncthreads();
        }
        if (t == 0) g_wsum = red[0];
    }
}

// =====================================================================
// K2: FUSED {softmax(t-1): argmax + logp-write + gather} + gates GEMM +
// LSTM activation. grid 128, block 256.
// Smem x layout uses XOR-(kk>>2) column swizzle: logical b lives at
// physical column b ^ (((row>>2)&7)<<2). Readers apply same xor =>
// logical mapping (and hence all arithmetic order) identical to R10.
// =====================================================================
__global__ __launch_bounds__(256) void gatesact_kernel(
    const float* __restrict__ W_ih, const float* __restrict__ b_ih,
    const float* __restrict__ b_hh, const float* __restrict__ te,
    float* __restrict__ out, int step, int write_idx)
{
    __shared__ __align__(16) float  s_x[4 * 32 * 64];    // 32KB swizzled [row][col]
    __shared__ __align__(16) float2 s_w2[12 * 4 * 32];   // 12KB [r][ks][kk] (w,w) pairs
    __shared__ int   s_idx[BB];
    __shared__ float s_red[8];
    __shared__ float s_lse;

    const int bid = blockIdx.x, t = threadIdx.x;
    const int e0 = bid * 4;
    const int ks = t >> 6, el = (t >> 4) & 3, bq = t & 15;
    const int w = t >> 5, lane = t & 31;

    // ============ prologue: softmax work for step-1 (step>0) ============
    if (step > 0) {
        __shared__ float s_maxv[BB];
        // phase 1: argmax per b (warp w owns b = w*8+i), all blocks redundant
#pragma unroll
        for (int i = 0; i < 8; i++) {
            const int b = w * 8 + i;
            const float* sr = g_scores + b * NN;
            float m = -3.4e38f; int mi = 0;
#pragma unroll
            for (int j = 0; j < 4; j++) {
                const int f4i = j * 32 + lane;          // contiguous per instr
                float4 v = __ldg((const float4*)sr + f4i);
                const int nb = f4i * 4;
                if (v.x > m || (v.x == m && nb     < mi)) { m = v.x; mi = nb;     }
                if (v.y > m || (v.y == m && nb + 1 < mi)) { m = v.y; mi = nb + 1; }
                if (v.z > m || (v.z == m && nb + 2 < mi)) { m = v.z; mi = nb + 2; }
                if (v.w > m || (v.w == m && nb + 3 < mi)) { m = v.w; mi = nb + 3; }
            }
#pragma unroll
            for (int o = 16; o; o >>= 1) {
                const float om = __shfl_xor_sync(0xffffffffu, m, o);
                const int   oi = __shfl_xor_sync(0xffffffffu, mi, o);
                if (om > m || (om == m && oi < mi)) { m = om; mi = oi; }
            }
            if (lane == 0) { s_idx[b] = mi; s_maxv[b] = m; }
        }
        __syncthreads();

        // phase 2: blocks 0..63 compute lse + write logp for b = bid.
        // All blocks execute the syncs (uniform); others compute on zeros.
        float s0 = 0.f, s1 = 0.f, mm = 0.f;
        if (bid < BB) {
            mm = s_maxv[bid];
            s0 = __ldg(&g_scores[bid * NN + t]);
            s1 = __ldg(&g_scores[bid * NN + t + 256]);
        }
        float sum = expf(s0 - mm) + expf(s1 - mm);
#pragma unroll
        for (int o = 16; o; o >>= 1) sum += __shfl_xor_sync(0xffffffffu, sum, o);
        if (lane == 0) s_red[w] = sum;
        __syncthreads();
        if (t == 0) {
            float v2 = 0.f;
#pragma unroll
            for (int i = 0; i < 8; i++) v2 += s_red[i];
            s_lse = mm + logf(v2);
        }
        __syncthreads();
        if (bid < BB) {
            const float lse = s_lse;
            float* orow = out + ((size_t)bid * TT + (step - 1)) * NN;
            orow[t]       = s0 - lse;
            orow[t + 256] = s1 - lse;
            if (write_idx && t == 0)
                out[(size_t)BB * TT * NN + bid * TT + (step - 1)] = (float)s_idx[bid];
        }
        __syncthreads();
    }

    // ============ gates GEMM (k in 4 internal quarters) ============
    ull acc[3][2];
#pragma unroll
    for (int g = 0; g < 3; g++) { acc[g][0] = 0ULL; acc[g][1] = 0ULL; }

    const int g_kss = lane >> 3, g_f4 = lane & 7;   // gather lane mapping

    for (int c = 0; c < 8; c++) {
        // ---- stage x into swizzled layout ----
        if (step == 0) {
#pragma unroll
            for (int i = 0; i < 8; i++) {
                const int i4 = i * 256 + t;
                const int b4 = i4 & 15, kk = (i4 >> 4) & 31, kss = i4 >> 9;
                const int row  = kss * 32 + kk;
                const int xorv = ((kk >> 2) & 7) << 2;
                float4 v = __ldg((const float4*)&g_dec_t[(kss * 256 + c * 32 + kk) * BB + b4 * 4]);
                *(float4*)&s_x[row * 64 + ((b4 * 4) ^ xorv)] = v;
            }
        } else {
            // gather te[b, idx_b, kslice]: warp w owns b = w*8+i, k-coalesced
#pragma unroll
            for (int i = 0; i < 8; i++) {
                const int b = w * 8 + i;
                const float* trow = te + ((size_t)b * NN + s_idx[b]) * DD;
                float4 v = __ldg((const float4*)(trow + g_kss * 256 + c * 32 + g_f4 * 4));
                const int row0 = g_kss * 32 + g_f4 * 4;
                const int col  = b ^ (g_f4 << 2);
                s_x[(row0 + 0) * 64 + col] = v.x;
                s_x[(row0 + 1) * 64 + col] = v.y;
                s_x[(row0 + 2) * 64 + col] = v.z;
                s_x[(row0 + 3) * 64 + col] = v.w;
            }
        }
        // ---- stage w (duplicated pairs): 1536 floats ----
#pragma unroll
        for (int j = 0; j < 6; j++) {
            const int idx = j * 256 + t;
            const int kk = idx & 31, kss = (idx >> 5) & 3, r = idx >> 7;  // r<12
            const int e = e0 + r / 3;
            const int gi = r % 3;
            const int grow = (gi == 0 ? 0 : (gi == 1 ? 2 * EE : 3 * EE)) + e;
            const float wv = __ldg(&W_ih[(size_t)grow * DD + kss * 256 + c * 32 + kk]);
            s_w2[(r * 4 + kss) * 32 + kk] = make_float2(wv, wv);
        }
        __syncthreads();

#pragma unroll
        for (int kk = 0; kk < 32; kk++) {
            const int xorv = ((kk >> 2) & 7) << 2;
            const float* xp = &s_x[(ks * 32 + kk) * 64 + ((bq * 4) ^ xorv)];
            ull a0 = *(const ull*)xp;
            ull a1 = *(const ull*)(xp + 2);
#pragma unroll
            for (int g = 0; g < 3; g++) {
                ull wp = *(const ull*)&s_w2[((el * 3 + g) * 4 + ks) * 32 + kk];
                ffma2(acc[g][0], wp, a0);
                ffma2(acc[g][1], wp, a1);
            }
        }
        __syncthreads();
    }

    // write partials into s_x (reused as red[ks][g][el][b], plain layout)
#pragma unroll
    for (int g = 0; g < 3; g++) {
        float a, b2, c2, d2;
        unpack2(acc[g][0], a, b2);
        unpack2(acc[g][1], c2, d2);
        *(float4*)&s_x[(((ks * 3 + g) * 4 + el) * 64) + bq * 4] = make_float4(a, b2, c2, d2);
    }
    __syncthreads();

    // reduce 4 k-partials (fixed order) + biases + activation; coalesced tail
    {
        const int el2 = t >> 6, b = t & 63;
        const int e = e0 + el2;
        float gi = __ldg(&b_ih[e])          + __ldg(&b_hh[e]);
        float gg = __ldg(&b_ih[2 * EE + e]) + __ldg(&b_hh[2 * EE + e]);
        float go = __ldg(&b_ih[3 * EE + e]) + __ldg(&b_hh[3 * EE + e]);
#pragma unroll
        for (int kq = 0; kq < 4; kq++) {
            gi += s_x[((kq * 3 + 0) * 4 + el2) * 64 + b];
            gg += s_x[((kq * 3 + 1) * 4 + el2) * 64 + b];
            go += s_x[((kq * 3 + 2) * 4 + el2) * 64 + b];
        }
        const float c  = (1.f / (1.f + expf(-gi))) * tanhf(gg);
        g_hx_t[e * BB + b] = (1.f / (1.f + expf(-go))) * tanhf(c);
    }
}

// =====================================================================
// K3: q partials, single staging pass. grid 128, block 256. (exact R10)
// =====================================================================
__global__ __launch_bounds__(256) void q_gemm_kernel(const float* __restrict__ Wd)
{
    const int eb = blockIdx.x & 31, ks = blockIdx.x >> 5;
    const int e0 = eb * 16, kbase = ks * 128;

    __shared__ __align__(16) float xs[128][64];   // 32KB
    __shared__ __align__(16) float ws[16][128];   // 8KB

    const int t = threadIdx.x, ec = t >> 4, bq = t & 15;

#pragma unroll
    for (int i = 0; i < 8; i++) {
        const int i4 = i * 256 + t;
        const int kk = i4 >> 4, b4 = i4 & 15;
        *(float4*)&xs[kk][b4 * 4] =
            __ldg((const float4*)&g_hx_t[(kbase + kk) * BB + b4 * 4]);
    }
#pragma unroll
    for (int i = 0; i < 2; i++) {
        const int i4 = i * 256 + t;
        const int ee = i4 >> 5, k4 = i4 & 31;
        *(float4*)&ws[ee][k4 * 4] =
            __ldg((const float4*)&Wd[(size_t)(e0 + ee) * EE + kbase + k4 * 4]);
    }
    __syncthreads();

    ull acc0 = 0ULL, acc1 = 0ULL;
#pragma unroll 16
    for (int kk = 0; kk < 128; kk++) {
        float4 xv = *(const float4*)&xs[kk][bq * 4];
        const float w = ws[ec][kk];
        ull wp = pack2(w, w);
        ffma2(acc0, wp, pack2(xv.x, xv.y));
        ffma2(acc1, wp, pack2(xv.z, xv.w));
    }

    float a, b2, c2, d2;
    unpack2(acc0, a, b2);
    unpack2(acc1, c2, d2);
    const int b0 = bq * 4, e = e0 + ec;
    g_qpart[ks][b0 + 0][e] = a;
    g_qpart[ks][b0 + 1][e] = b2;
    g_qpart[ks][b0 + 2][e] = c2;
    g_qpart[ks][b0 + 3][e] = d2;
}

// =====================================================================
// K4: scores. grid (8, 64), block 256. (exact R10)
// =====================================================================
__global__ __launch_bounds__(256) void attn_kernel(
    const float* __restrict__ wr, const float* __restrict__ bd,
    const float* __restrict__ br)
{
    __shared__ float qc[EE];
    __shared__ float wsm[EE];
    __shared__ float part[4][64];

    const int b  = blockIdx.y;
    const int t  = threadIdx.x;
    const int nl = t & 63;
    const int qr = t >> 6;
    const int n  = blockIdx.x * 64 + nl;

#pragma unroll
    for (int j = 0; j < 2; j++) {
        const int e = j * 256 + t;
        const float q = __ldg(&bd[e]) + g_qpart[0][b][e] + g_qpart[1][b][e]
                        + g_qpart[2][b][e] + g_qpart[3][b][e];
        qc[e]  = C2L * q;
        wsm[e] = __ldg(&wr[e]);
    }
    __syncthreads();

    const float* p = g_enc + ((size_t)b * EE + qr * 128) * NN + n;
    float acc = 0.f;
#pragma unroll 8
    for (int e = 0; e < 128; e++) {
        const float v  = __ldg(p + (size_t)e * NN);
        const int   eg = (qr << 7) + e;
        const float a  = fmaf(C2L, v, qc[eg]);
        const float tt = ex2a(a);
        const float u  = rcpa(tt + 1.f);
        acc = fmaf(wsm[eg], u, acc);
    }
    part[qr][nl] = acc;
    __syncthreads();

    if (t < 64) {
        const float s = g_wsum
                      - 2.f * (part[0][t] + part[1][t] + part[2][t] + part[3][t])
                      + __ldg(br);
        g_scores[b * NN + blockIdx.x * 64 + t] = s;
    }
}

// =====================================================================
// K5: final-step log_softmax + argmax + (harmless) gather.
// grid 64, block 512. Launched ONCE after the loop. (exact R10)
// =====================================================================
__global__ __launch_bounds__(512) void softmax_kernel(
    const float* __restrict__ te, float* __restrict__ out,
    int t_step, int write_idx)
{
    __shared__ float wm[16];
    __shared__ int   wi[16];
    __shared__ float wsum_[16];
    __shared__ float s_m;
    __shared__ int   s_i;
    __shared__ float s_lse;

    const int b = blockIdx.x, n = threadIdx.x;
    const int lane = n & 31, w = n >> 5;

    const float s = g_scores[b * NN + n];

    float m = s; int mi = n;
#pragma unroll
    for (int o = 16; o; o >>= 1) {
        const float om = __shfl_xor_sync(0xffffffffu, m, o);
        const int   oi = __shfl_xor_sync(0xffffffffu, mi, o);
        if (om > m || (om == m && oi < mi)) { m = om; mi = oi; }
    }
    if (lane == 0) { wm[w] = m; wi[w] = mi; }
    __syncthreads();
    if (w == 0) {
        float m2 = (lane < 16) ? wm[lane] : -3.4e38f;
        int   i2 = (lane < 16) ? wi[lane] : 0;
#pragma unroll
        for (int o = 8; o; o >>= 1) {
            const float om = __shfl_xor_sync(0xffffffffu, m2, o);
            const int   oi = __shfl_xor_sync(0xffffffffu, i2, o);
            if (om > m2 || (om == m2 && oi < i2)) { m2 = om; i2 = oi; }
        }
        if (lane == 0) { s_m = m2; s_i = i2; }
    }
    __syncthreads();
    const float mm  = s_m;
    const int   idx = s_i;

    float sum = expf(s - mm);
#pragma unroll
    for (int o = 16; o; o >>= 1) sum += __shfl_xor_sync(0xffffffffu, sum, o);
    if (lane == 0) wsum_[w] = sum;
    __syncthreads();
    if (w == 0) {
        float s2 = (lane < 16) ? wsum_[lane] : 0.f;
#pragma unroll
        for (int o = 8; o; o >>= 1) s2 += __shfl_xor_sync(0xffffffffu, s2, o);
        if (lane == 0) s_lse = mm + logf(s2);
    }
    __syncthreads();

    out[((size_t)b * TT + t_step) * NN + n] = s - s_lse;

    const float* src = te + ((size_t)b * NN + idx) * DD;
    g_dec_t[n * BB + b]          = src[n];
    g_dec_t[(n + 512) * BB + b]  = src[n + 512];

    if (write_idx && n == 0)
        out[(size_t)BB * TT * NN + b * TT + t_step] = (float)idx;
}

// =====================================================================
extern "C" void kernel_launch(void* const* d_in, const int* in_sizes, int n_in,
                              void* d_out, int out_size)
{
    const float* te     = (const float*)d_in[0];   // [64,512,1024]
    const float* encdoc = (const float*)d_in[1];   // [64,1024]
    const float* W_ih   = (const float*)d_in[2];   // [2048,1024]
    const float* b_ih   = (const float*)d_in[3];   // [2048]
    const float* b_hh   = (const float*)d_in[4];   // [2048]
    const float* Wd     = (const float*)d_in[5];   // [512,512]
    const float* bd     = (const float*)d_in[6];   // [512]
    const float* We     = (const float*)d_in[7];   // [512,1024]
    const float* be     = (const float*)d_in[8];   // [512]
    const float* wr     = (const float*)d_in[9];   // [1,512]
    const float* br     = (const float*)d_in[10];  // [1]

    float* out = (float*)d_out;
    const int write_idx = (out_size >= BB * TT * NN + BB * TT) ? 1 : 0;

    // Phase 1: loop-invariant encoder projection, stored [b][e][n]
    enc_kernel<<<dim3(NN / 128, EE / 128, BB), 256>>>(te, We, be);

    // Step-0 decoder input (transposed) + wr sum
    init_kernel<<<BB, 256>>>(encdoc, wr);

    // Sequential pointer decode: 3 kernels per step
    // gatesact(t) also performs softmax/argmax/logp-write/gather for step t-1
    for (int t = 0; t < TT; t++) {
        gatesact_kernel<<<128, 256>>>(W_ih, b_ih, b_hh, te, out, t, write_idx);
        q_gemm_kernel<<<128, 256>>>(Wd);
        attn_kernel<<<dim3(NN / 64, BB), 256>>>(wr, bd, br);
    }
    // Final step's softmax/argmax outputs
    softmax_kernel<<<BB, 512>>>(te, out, TT - 1, write_idx);
}

// round 13
// speedup vs baseline: 1.2884x; 1.2884x over previous
#include <cuda_runtime.h>
#include <cuda_bf16.h>

// Problem constants
#define BB 64      // batch
#define NN 512     // tokens
#define EE 512     // embed dim
#define DD 1024    // 2E
#define TT 64      // decode steps

typedef unsigned long long ull;

// ---------------- device scratch ----------------
__device__ float g_enc[(size_t)BB * EE * NN];   // [b][e][n]  64 MB, L2-resident
__device__ float g_dec_t[DD * BB];              // decoder input, TRANSPOSED [k][b]
__device__ float g_hx_t[EE * BB];               // hx transposed [e(=k')][b]
__device__ float g_qpart[4][BB][EE];            // q partials [ks][b][e]
__device__ float g_scores[BB * NN];
__device__ float g_wsum;                        // sum of wr
__device__ float g_amaxv[BB][8];                // per-(b, n-chunk) argmax partial val
__device__ int   g_amaxi[BB][8];                // per-(b, n-chunk) argmax partial idx
__device__ float g_gmax[BB];                    // global max per b (for lse)

// ---------------- packed fp32x2 helpers (sm_103a FFMA2) ----------------
__device__ __forceinline__ ull pack2(float x, float y) {
    ull r; asm("mov.b64 %0, {%1,%2};" : "=l"(r) : "f"(x), "f"(y)); return r;
}
__device__ __forceinline__ void unpack2(ull v, float& x, float& y) {
    asm("mov.b64 {%0,%1}, %2;" : "=f"(x), "=f"(y) : "l"(v));
}
__device__ __forceinline__ void ffma2(ull& d, ull a, ull b) {
    asm("fma.rn.f32x2 %0, %1, %2, %0;" : "+l"(d) : "l"(a), "l"(b));
}
__device__ __forceinline__ float ex2a(float x) {
    float r; asm("ex2.approx.f32 %0, %1;" : "=f"(r) : "f"(x)); return r;
}
__device__ __forceinline__ float rcpa(float x) {
    float r; asm("rcp.approx.f32 %0, %1;" : "=f"(r) : "f"(x)); return r;
}

#define C2L 2.885390081777926f   // 2*log2(e)

// =====================================================================
// K1: enc[b][e][n] = be[e] + sum_d te[b][n][d] * We[e][d]
// (EXACT R10 version — measured 753us, ~fp32 FFMA2 roofline)
// =====================================================================
__global__ __launch_bounds__(256) void enc_kernel(
    const float* __restrict__ te, const float* __restrict__ We,
    const float* __restrict__ be)
{
    const int b  = blockIdx.z;
    const int n0 = blockIdx.x * 128;
    const int e0 = blockIdx.y * 128;

    __shared__ __align__(16) float As[16][132];
    __shared__ __align__(16) float Bs[16][132];

    const int tid = threadIdx.x;
    const int ty  = tid >> 4;
    const int tx  = tid & 15;

    ull acc[8][4];
#pragma unroll
    for (int i = 0; i < 8; i++)
#pragma unroll
        for (int j = 0; j < 4; j++) acc[i][j] = 0ULL;

    const int lrow = tid >> 2;
    const int lk4  = (tid & 3) * 4;
    const float* Aptr = We + (size_t)(e0 + lrow) * DD + lk4;
    const float* Bptr = te + ((size_t)b * NN + (n0 + lrow)) * DD + lk4;

    for (int k0 = 0; k0 < DD; k0 += 16) {
        float4 a0 = *(const float4*)(Aptr + k0);
        float4 a1 = *(const float4*)(Aptr + k0 + (size_t)64 * DD);
        float4 c0 = *(const float4*)(Bptr + k0);
        float4 c1 = *(const float4*)(Bptr + k0 + (size_t)64 * DD);
        As[lk4 + 0][lrow]      = a0.x; As[lk4 + 1][lrow]      = a0.y;
        As[lk4 + 2][lrow]      = a0.z; As[lk4 + 3][lrow]      = a0.w;
        As[lk4 + 0][lrow + 64] = a1.x; As[lk4 + 1][lrow + 64] = a1.y;
        As[lk4 + 2][lrow + 64] = a1.z; As[lk4 + 3][lrow + 64] = a1.w;
        Bs[lk4 + 0][lrow]      = c0.x; Bs[lk4 + 1][lrow]      = c0.y;
        Bs[lk4 + 2][lrow]      = c0.z; Bs[lk4 + 3][lrow]      = c0.w;
        Bs[lk4 + 0][lrow + 64] = c1.x; Bs[lk4 + 1][lrow + 64] = c1.y;
        Bs[lk4 + 2][lrow + 64] = c1.z; Bs[lk4 + 3][lrow + 64] = c1.w;
        __syncthreads();

#pragma unroll
        for (int kk = 0; kk < 16; kk++) {
            float4 av0 = *(const float4*)&As[kk][ty * 8];
            float4 av1 = *(const float4*)&As[kk][ty * 8 + 4];
            float4 bv0 = *(const float4*)&Bs[kk][tx * 8];
            float4 bv1 = *(const float4*)&Bs[kk][tx * 8 + 4];
            ull bp0 = pack2(bv0.x, bv0.y);
            ull bp1 = pack2(bv0.z, bv0.w);
            ull bp2 = pack2(bv1.x, bv1.y);
            ull bp3 = pack2(bv1.z, bv1.w);
            float av[8] = {av0.x, av0.y, av0.z, av0.w, av1.x, av1.y, av1.z, av1.w};
#pragma unroll
            for (int i = 0; i < 8; i++) {
                ull ad = pack2(av[i], av[i]);
                ffma2(acc[i][0], ad, bp0);
                ffma2(acc[i][1], ad, bp1);
                ffma2(acc[i][2], ad, bp2);
                ffma2(acc[i][3], ad, bp3);
            }
        }
        __syncthreads();
    }

#pragma unroll
    for (int i = 0; i < 8; i++) {
        const int e = e0 + ty * 8 + i;
        const float bias = __ldg(&be[e]);
        float* orow = g_enc + ((size_t)b * EE + e) * NN + n0 + tx * 8;
#pragma unroll
        for (int j = 0; j < 4; j++) {
            float x, y;
            unpack2(acc[i][j], x, y);
            float2 v = make_float2(x + bias, y + bias);
            *(float2*)(orow + 2 * j) = v;
        }
    }
}

// =====================================================================
// K0: g_dec_t[k][b] <- encoded_document[b][k]; block 0 also reduces wr.
// grid 64, block 256
// =====================================================================
__global__ __launch_bounds__(256) void init_kernel(
    const float* __restrict__ encdoc, const float* __restrict__ wr)
{
    const int b = blockIdx.x, t = threadIdx.x;
#pragma unroll
    for (int i = 0; i < 4; i++) {
        const int k = i * 256 + t;
        g_dec_t[k * BB + b] = encdoc[(size_t)b * DD + k];
    }
    if (b == 0) {
        __shared__ float red[256];
        red[t] = __ldg(&wr[t]) + __ldg(&wr[t + 256]);
        __syncthreads();
#pragma unroll
        for (int o = 128; o > 0; o >>= 1) {
            if (t < o) red[t] += red[t + o];
            __syncthreads();
        }
        if (t == 0) g_wsum = red[0];
    }
}

// =====================================================================
// K2: gates GEMM (full k, internal 4-way k-split reduced in smem) +
// fused LSTM activation. grid 128, block 256. (EXACT R10)
// =====================================================================
__global__ __launch_bounds__(256) void gatesact_kernel(
    const float* __restrict__ W_ih, const float* __restrict__ b_ih,
    const float* __restrict__ b_hh)
{
    __shared__ __align__(16) float  s_x[4 * 32 * 64];    // 32KB [ks][kk][b]; reused as red
    __shared__ __align__(16) float2 s_w2[12 * 4 * 32];   // 12KB [r][ks][kk] (w,w) pairs

    const int bid = blockIdx.x, t = threadIdx.x;
    const int e0 = bid * 4;
    const int ks = t >> 6, el = (t >> 4) & 3, bq = t & 15;

    ull acc[3][2];
#pragma unroll
    for (int g = 0; g < 3; g++) { acc[g][0] = 0ULL; acc[g][1] = 0ULL; }

    for (int c = 0; c < 8; c++) {
#pragma unroll
        for (int i = 0; i < 8; i++) {
            const int i4 = i * 256 + t;
            const int b4 = i4 & 15, kk = (i4 >> 4) & 31, kss = i4 >> 9;
            float4 v = __ldg((const float4*)&g_dec_t[(kss * 256 + c * 32 + kk) * BB + b4 * 4]);
            *(float4*)&s_x[(kss * 32 + kk) * 64 + b4 * 4] = v;
        }
#pragma unroll
        for (int j = 0; j < 6; j++) {
            const int idx = j * 256 + t;
            const int kk = idx & 31, kss = (idx >> 5) & 3, r = idx >> 7;  // r<12
            const int e = e0 + r / 3;
            const int gi = r % 3;
            const int grow = (gi == 0 ? 0 : (gi == 1 ? 2 * EE : 3 * EE)) + e;
            const float w = __ldg(&W_ih[(size_t)grow * DD + kss * 256 + c * 32 + kk]);
            s_w2[(r * 4 + kss) * 32 + kk] = make_float2(w, w);
        }
        __syncthreads();

#pragma unroll
        for (int kk = 0; kk < 32; kk++) {
            const float* xp = &s_x[(ks * 32 + kk) * 64 + bq * 4];
            ull a0 = *(const ull*)xp;
            ull a1 = *(const ull*)(xp + 2);
#pragma unroll
            for (int g = 0; g < 3; g++) {
                ull wp = *(const ull*)&s_w2[((el * 3 + g) * 4 + ks) * 32 + kk];
                ffma2(acc[g][0], wp, a0);
                ffma2(acc[g][1], wp, a1);
            }
        }
        __syncthreads();
    }

#pragma unroll
    for (int g = 0; g < 3; g++) {
        float a, b2, c2, d2;
        unpack2(acc[g][0], a, b2);
        unpack2(acc[g][1], c2, d2);
        *(float4*)&s_x[(((ks * 3 + g) * 4 + el) * 64) + bq * 4] = make_float4(a, b2, c2, d2);
    }
    __syncthreads();

    {
        const int el2 = t >> 6, b = t & 63;
        const int e = e0 + el2;
        float gi = __ldg(&b_ih[e])          + __ldg(&b_hh[e]);
        float gg = __ldg(&b_ih[2 * EE + e]) + __ldg(&b_hh[2 * EE + e]);
        float go = __ldg(&b_ih[3 * EE + e]) + __ldg(&b_hh[3 * EE + e]);
#pragma unroll
        for (int kq = 0; kq < 4; kq++) {
            gi += s_x[((kq * 3 + 0) * 4 + el2) * 64 + b];
            gg += s_x[((kq * 3 + 1) * 4 + el2) * 64 + b];
            go += s_x[((kq * 3 + 2) * 4 + el2) * 64 + b];
        }
        const float c  = (1.f / (1.f + expf(-gi))) * tanhf(gg);
        g_hx_t[e * BB + b] = (1.f / (1.f + expf(-go))) * tanhf(c);
    }
}

// =====================================================================
// K3: q partials, single staging pass + APPENDED logp-write for step-1.
// grid 128, block 256. GEMM part exact R10; blocks 0..63 additionally
// compute log_softmax row for b=bid using g_gmax (from pick(t-1)) and
// scores(t-1) (still intact — attn(t) runs later).
// =====================================================================
__global__ __launch_bounds__(256) void q_gemm_kernel(
    const float* __restrict__ Wd, float* __restrict__ out, int step)
{
    const int eb = blockIdx.x & 31, ks = blockIdx.x >> 5;
    const int e0 = eb * 16, kbase = ks * 128;

    __shared__ __align__(16) float xs[128][64];   // 32KB
    __shared__ __align__(16) float ws[16][128];   // 8KB
    __shared__ float s_red[8];
    __shared__ float s_lse;

    const int t = threadIdx.x, ec = t >> 4, bq = t & 15;

#pragma unroll
    for (int i = 0; i < 8; i++) {
        const int i4 = i * 256 + t;
        const int kk = i4 >> 4, b4 = i4 & 15;
        *(float4*)&xs[kk][b4 * 4] =
            __ldg((const float4*)&g_hx_t[(kbase + kk) * BB + b4 * 4]);
    }
#pragma unroll
    for (int i = 0; i < 2; i++) {
        const int i4 = i * 256 + t;
        const int ee = i4 >> 5, k4 = i4 & 31;
        *(float4*)&ws[ee][k4 * 4] =
            __ldg((const float4*)&Wd[(size_t)(e0 + ee) * EE + kbase + k4 * 4]);
    }
    __syncthreads();

    ull acc0 = 0ULL, acc1 = 0ULL;
#pragma unroll 16
    for (int kk = 0; kk < 128; kk++) {
        float4 xv = *(const float4*)&xs[kk][bq * 4];
        const float w = ws[ec][kk];
        ull wp = pack2(w, w);
        ffma2(acc0, wp, pack2(xv.x, xv.y));
        ffma2(acc1, wp, pack2(xv.z, xv.w));
    }

    float a, b2, c2, d2;
    unpack2(acc0, a, b2);
    unpack2(acc1, c2, d2);
    const int b0 = bq * 4, e = e0 + ec;
    g_qpart[ks][b0 + 0][e] = a;
    g_qpart[ks][b0 + 1][e] = b2;
    g_qpart[ks][b0 + 2][e] = c2;
    g_qpart[ks][b0 + 3][e] = d2;

    // ---- appendix: logp row for step-1, blocks 0..63 only ----
    if (blockIdx.x < BB && step > 0) {
        const int b = blockIdx.x;
        const int lane = t & 31, w2 = t >> 5;
        const float gm = g_gmax[b];
        const float s0 = __ldg(&g_scores[b * NN + t]);
        const float s1 = __ldg(&g_scores[b * NN + t + 256]);
        float sum = expf(s0 - gm) + expf(s1 - gm);
#pragma unroll
        for (int o = 16; o; o >>= 1) sum += __shfl_xor_sync(0xffffffffu, sum, o);
        if (lane == 0) s_red[w2] = sum;
        __syncthreads();
        if (t == 0) {
            float v2 = 0.f;
#pragma unroll
            for (int i = 0; i < 8; i++) v2 += s_red[i];
            s_lse = gm + logf(v2);
        }
        __syncthreads();
        const float lse = s_lse;
        float* orow = out + ((size_t)b * TT + (step - 1)) * NN;
        orow[t]       = s0 - lse;
        orow[t + 256] = s1 - lse;
    }
}

// =====================================================================
// K4: scores + argmax partial per block. grid (8, 64), block 256.
// (R10 + ~20-instr tail)
// =====================================================================
__global__ __launch_bounds__(256) void attn_kernel(
    const float* __restrict__ wr, const float* __restrict__ bd,
    const float* __restrict__ br)
{
    __shared__ float qc[EE];
    __shared__ float wsm[EE];
    __shared__ float part[4][64];
    __shared__ float s_mv[2];
    __shared__ int   s_mi[2];

    const int b  = blockIdx.y;
    const int t  = threadIdx.x;
    const int nl = t & 63;
    const int qr = t >> 6;
    const int n  = blockIdx.x * 64 + nl;

#pragma unroll
    for (int j = 0; j < 2; j++) {
        const int e = j * 256 + t;
        const float q = __ldg(&bd[e]) + g_qpart[0][b][e] + g_qpart[1][b][e]
                        + g_qpart[2][b][e] + g_qpart[3][b][e];
        qc[e]  = C2L * q;
        wsm[e] = __ldg(&wr[e]);
    }
    __syncthreads();

    const float* p = g_enc + ((size_t)b * EE + qr * 128) * NN + n;
    float acc = 0.f;
#pragma unroll 8
    for (int e = 0; e < 128; e++) {
        const float v  = __ldg(p + (size_t)e * NN);
        const int   eg = (qr << 7) + e;
        const float a  = fmaf(C2L, v, qc[eg]);
        const float tt = ex2a(a);
        const float u  = rcpa(tt + 1.f);
        acc = fmaf(wsm[eg], u, acc);
    }
    part[qr][nl] = acc;
    __syncthreads();

    if (t < 64) {
        const float s = g_wsum
                      - 2.f * (part[0][t] + part[1][t] + part[2][t] + part[3][t])
                      + __ldg(br);
        g_scores[b * NN + blockIdx.x * 64 + t] = s;

        // argmax partial (warps 0,1 only; first-index ties)
        float m = s; int mi = blockIdx.x * 64 + t;
        const int lane = t & 31;
#pragma unroll
        for (int o = 16; o; o >>= 1) {
            const float om = __shfl_xor_sync(0xffffffffu, m, o);
            const int   oi = __shfl_xor_sync(0xffffffffu, mi, o);
            if (om > m || (om == m && oi < mi)) { m = om; mi = oi; }
        }
        if (lane == 0) { s_mv[t >> 5] = m; s_mi[t >> 5] = mi; }
    }
    __syncthreads();
    if (t == 0) {
        float m = s_mv[0]; int mi = s_mi[0];
        if (s_mv[1] > m || (s_mv[1] == m && s_mi[1] < mi)) { m = s_mv[1]; mi = s_mi[1]; }
        g_amaxv[b][blockIdx.x] = m;
        g_amaxi[b][blockIdx.x] = mi;
    }
}

// =====================================================================
// K5: pick — reduce 8 argmax partials (fixed nc order), gather te row
// into g_dec_t, write idx output, store g_gmax. grid 64, block 256.
// =====================================================================
__global__ __launch_bounds__(256) void pick_kernel(
    const float* __restrict__ te, float* __restrict__ out,
    int step, int write_idx)
{
    __shared__ int s_idx;

    const int b = blockIdx.x, t = threadIdx.x;

    if (t == 0) {
        float m = g_amaxv[b][0]; int mi = g_amaxi[b][0];
#pragma unroll
        for (int nc = 1; nc < 8; nc++) {
            const float v = g_amaxv[b][nc];
            const int   i = g_amaxi[b][nc];
            if (v > m || (v == m && i < mi)) { m = v; mi = i; }
        }
        s_idx = mi;
        g_gmax[b] = m;
        if (write_idx)
            out[(size_t)BB * TT * NN + b * TT + step] = (float)mi;
    }
    __syncthreads();
    const int idx = s_idx;

    const float* src = te + ((size_t)b * NN + idx) * DD;
#pragma unroll
    for (int i = 0; i < 4; i++) {
        const int k = i * 256 + t;
        g_dec_t[k * BB + b] = __ldg(&src[k]);
    }
}

// =====================================================================
// K6: final logp row for step TT-1 (same code as q_gemm appendix).
// grid 64, block 256. Launched once after the loop.
// =====================================================================
__global__ __launch_bounds__(256) void finish_kernel(float* __restrict__ out)
{
    __shared__ float s_red[8];
    __shared__ float s_lse;

    const int b = blockIdx.x, t = threadIdx.x;
    const int lane = t & 31, w2 = t >> 5;
    const float gm = g_gmax[b];
    const float s0 = __ldg(&g_scores[b * NN + t]);
    const float s1 = __ldg(&g_scores[b * NN + t + 256]);
    float sum = expf(s0 - gm) + expf(s1 - gm);
#pragma unroll
    for (int o = 16; o; o >>= 1) sum += __shfl_xor_sync(0xffffffffu, sum, o);
    if (lane == 0) s_red[w2] = sum;
    __syncthreads();
    if (t == 0) {
        float v2 = 0.f;
#pragma unroll
        for (int i = 0; i < 8; i++) v2 += s_red[i];
        s_lse = gm + logf(v2);
    }
    __syncthreads();
    const float lse = s_lse;
    float* orow = out + ((size_t)b * TT + (TT - 1)) * NN;
    orow[t]       = s0 - lse;
    orow[t + 256] = s1 - lse;
}

// =====================================================================
extern "C" void kernel_launch(void* const* d_in, const int* in_sizes, int n_in,
                              void* d_out, int out_size)
{
    const float* te     = (const float*)d_in[0];   // [64,512,1024]
    const float* encdoc = (const float*)d_in[1];   // [64,1024]
    const float* W_ih   = (const float*)d_in[2];   // [2048,1024]
    const float* b_ih   = (const float*)d_in[3];   // [2048]
    const float* b_hh   = (const float*)d_in[4];   // [2048]
    const float* Wd     = (const float*)d_in[5];   // [512,512]
    const float* bd     = (const float*)d_in[6];   // [512]
    const float* We     = (const float*)d_in[7];   // [512,1024]
    const float* be     = (const float*)d_in[8];   // [512]
    const float* wr     = (const float*)d_in[9];   // [1,512]
    const float* br     = (const float*)d_in[10];  // [1]

    float* out = (float*)d_out;
    const int write_idx = (out_size >= BB * TT * NN + BB * TT) ? 1 : 0;

    // Phase 1: loop-invariant encoder projection, stored [b][e][n]
    enc_kernel<<<dim3(NN / 128, EE / 128, BB), 256>>>(te, We, be);

    // Step-0 decoder input (transposed) + wr sum
    init_kernel<<<BB, 256>>>(encdoc, wr);

    // Sequential pointer decode: 4 kernels per step.
    // logp(t-1) rides inside q_gemm(t); pick handles argmax+gather only.
    for (int t = 0; t < TT; t++) {
        gatesact_kernel<<<128, 256>>>(W_ih, b_ih, b_hh);
        q_gemm_kernel<<<128, 256>>>(Wd, out, t);
        attn_kernel<<<dim3(NN / 64, BB), 256>>>(wr, bd, br);
        pick_kernel<<<BB, 256>>>(te, out, t, write_idx);
    }
    // Final step's logp row
    finish_kernel<<<BB, 256>>>(out);
}